// round 10
// baseline (speedup 1.0000x reference)
#include <cuda_runtime.h>

#define N_    1024
#define M_    1024
#define D_    128
#define NNZ_  32768
#define H_    256
#define GRID_ 1024

typedef unsigned long long u64;

// ---------------- device scratch (no allocations allowed) ----------------
// g_sum/g_cnt zeroed at load; phase 4 restores zero-state each invocation.
// g_bar[0]/g_bar[1] reset in phase 4; g_bar[2] reset in phase 0 of the NEXT
// invocation (ordered via barrier A's release-acquire chain).
__device__ int      g_cnt[M_];
__device__ unsigned g_bar[3];
__device__ __align__(16) float g_sum[M_ * D_];     // raw scatter sums [m][d]
__device__ __align__(16) float g_hxT[H_ * N_];     // [h][n]
__device__ __align__(16) float g_hebT[H_ * M_];    // [h][m] (incl /cnt and +b1)

// ---------------- small helpers ----------------
__device__ __forceinline__ u64 bcast2(float v) {
    u64 r;
    asm("mov.b64 %0, {%1, %1};" : "=l"(r) : "f"(v));
    return r;
}

__device__ __forceinline__ float2 unpack2(u64 v) {
    float lo, hi;
    asm("mov.b64 {%0, %1}, %2;" : "=f"(lo), "=f"(hi) : "l"(v));
    return make_float2(lo, hi);
}

// acc2 += relu(a2 + b2) * w2   (packed f32x2; relu on the scalar halves)
__device__ __forceinline__ void relu_fma2(u64 &acc, u64 a, u64 b, u64 w) {
    asm("{\n\t"
        ".reg .b64 t;\n\t"
        ".reg .f32 lo, hi;\n\t"
        "add.rn.f32x2 t, %1, %2;\n\t"
        "mov.b64 {lo, hi}, t;\n\t"
        "max.f32 lo, lo, 0f00000000;\n\t"
        "max.f32 hi, hi, 0f00000000;\n\t"
        "mov.b64 t, {lo, hi};\n\t"
        "fma.rn.f32x2 %0, t, %3, %0;\n\t"
        "}"
        : "+l"(acc) : "l"(a), "l"(b), "l"(w));
}

__device__ __forceinline__ float sigmoidf_fast(float x) {
    return 1.0f / (1.0f + __expf(-x));
}

// software grid barrier: all GRID_ blocks co-resident by construction
__device__ __forceinline__ void gbar(unsigned* ctr) {
    __syncthreads();
    if (threadIdx.x == 0) {
        unsigned prev;
        asm volatile("atom.add.release.gpu.u32 %0, [%1], 1;"
                     : "=r"(prev) : "l"(ctr) : "memory");
        if (prev + 1 < GRID_) {
            unsigned v;
            do {
                __nanosleep(128);
                asm volatile("ld.acquire.gpu.u32 %0, [%1];"
                             : "=r"(v) : "l"(ctr) : "memory");
            } while (v < GRID_);
        }
    }
    __syncthreads();
}

// ---------------- the one persistent kernel ----------------
__global__ __launch_bounds__(128, 7) void k_fused(const float* __restrict__ X,
                                                  const int* __restrict__ V,
                                                  const int* __restrict__ E,
                                                  const float* __restrict__ W1,
                                                  const float* __restrict__ b1,
                                                  const float* __restrict__ W2,
                                                  const float* __restrict__ b2p,
                                                  float* __restrict__ out) {
    // shared scratch, aliased per phase (4160 floats = 16.6 KB):
    // phase 2a (hxT):  As 32x65 (2080) + Ws 64x16 (1024)
    // phase 2b (hebT): As 16x65 (1040) + Ws 64x16 (1024)
    // phase 3  (main): hx 32x64 (2048) + heb 32x64 (2048) + w2 (64)
    __shared__ __align__(16) float sm[4160];

    int bid = blockIdx.x;
    int tid = threadIdx.x;

    // ======== phase 0: init out = b2; reset bar C (from prev invocation) ==
    if (bid == 0 && tid == 0) g_bar[2] = 0;   // ordered by barrier A chain
    {
        float b = __ldg(b2p);
        float4 bv = make_float4(b, b, b, b);
        float4* o4 = (float4*)out;
        o4[bid * 256 + tid]       = bv;
        o4[bid * 256 + 128 + tid] = bv;
    }

    // ======== phase 1 (role-split, pre-barrier-A) =========================
    if (bid < 512) {
        // --- role A: scatter (vector RED into g_sum), 16 edges per warp ---
        int gw   = bid * 4 + (tid >> 5);   // 2048 warps
        int lane = tid & 31;
        #pragma unroll
        for (int j = 0; j < 16; j++) {
            int edge = gw * 16 + j;
            int e = E[edge];
            int v = V[edge];
            float4 x = *(const float4*)&X[v * D_ + lane * 4];
            float* dst = &g_sum[e * D_ + lane * 4];
            asm volatile("red.global.add.v4.f32 [%0], {%1, %2, %3, %4};"
                         :: "l"(dst), "f"(x.x), "f"(x.y), "f"(x.z), "f"(x.w) : "memory");
            if (lane == 0) atomicAdd(&g_cnt[e], 1);
        }
    } else {
        // --- role B: hxT = (X @ W1[:D]).T, 512 tiles of 32n x 16h ---------
        int r  = bid - 512;
        int n0 = (r & 31) * 32;
        int h0 = (r >> 5) * 16;
        float* As = sm;          // [32][65]  (bank = n + k)
        float* Ws = sm + 2080;   // [64][16]
        int tn = tid & 7;        // n = tn*4 + i
        int th = tid >> 3;       // h (0..15)

        float acc[4] = {0.f, 0.f, 0.f, 0.f};
        for (int k0 = 0; k0 < D_; k0 += 64) {
            #pragma unroll
            for (int rr = 0; rr < 16; rr++) {
                int i  = rr * 128 + tid;
                int nn = i >> 6;
                int kk = i & 63;
                As[nn * 65 + kk] = X[(n0 + nn) * D_ + k0 + kk];
            }
            #pragma unroll
            for (int rr = 0; rr < 8; rr++) {
                int i  = rr * 128 + tid;
                int dk = i >> 4;
                int hh = i & 15;
                Ws[dk * 16 + hh] = W1[(k0 + dk) * H_ + h0 + hh];
            }
            __syncthreads();
            #pragma unroll 8
            for (int dk = 0; dk < 64; dk++) {
                float w = Ws[dk * 16 + th];
                #pragma unroll
                for (int i2 = 0; i2 < 4; i2++)
                    acc[i2] = fmaf(As[(tn * 4 + i2) * 65 + dk], w, acc[i2]);
            }
            __syncthreads();
        }
        #pragma unroll
        for (int i2 = 0; i2 < 4; i2++)
            g_hxT[(h0 + th) * N_ + n0 + tn * 4 + i2] = acc[i2];
    }

    gbar(&g_bar[0]);   // ======== barrier A ========

    // ======== phase 2b: hebT over ALL 1024 blocks (16m x 16h tiles) =======
    {
        int m0 = (bid & 63) * 16;
        int h0 = (bid >> 6) * 16;
        float* As = sm;          // [16][65]
        float* Ws = sm + 1040;   // [64][16]
        int tm = tid & 7;        // m = tm*2 + e
        int th = tid >> 3;       // h (0..15)

        float acc0 = 0.f, acc1 = 0.f;
        for (int k0 = 0; k0 < D_; k0 += 64) {
            #pragma unroll
            for (int rr = 0; rr < 8; rr++) {
                int i  = rr * 128 + tid;
                int mm = i >> 6;
                int kk = i & 63;
                As[mm * 65 + kk] = g_sum[(m0 + mm) * D_ + k0 + kk];
            }
            #pragma unroll
            for (int rr = 0; rr < 8; rr++) {
                int i  = rr * 128 + tid;
                int dk = i >> 4;
                int hh = i & 15;
                Ws[dk * 16 + hh] = W1[(D_ + k0 + dk) * H_ + h0 + hh];
            }
            __syncthreads();
            #pragma unroll 8
            for (int dk = 0; dk < 64; dk++) {
                float w = Ws[dk * 16 + th];
                acc0 = fmaf(As[(tm * 2) * 65 + dk],     w, acc0);
                acc1 = fmaf(As[(tm * 2 + 1) * 65 + dk], w, acc1);
            }
            __syncthreads();
        }
        int c0 = g_cnt[m0 + tm * 2];
        int c1 = g_cnt[m0 + tm * 2 + 1];
        float s0 = 1.0f / ((c0 > 0) ? (float)c0 : 1.0f);
        float s1 = 1.0f / ((c1 > 0) ? (float)c1 : 1.0f);
        float bb = b1[h0 + th];
        g_hebT[(h0 + th) * M_ + m0 + tm * 2]     = acc0 * s0 + bb;
        g_hebT[(h0 + th) * M_ + m0 + tm * 2 + 1] = acc1 * s1 + bb;
    }

    gbar(&g_bar[1]);   // ======== barrier B ========

    // ======== phase 3: main N x M x H contraction (exact R3 loop) =========
    {
        float* hx_s  = sm;           // [32][64]
        float* heb_s = sm + 2048;    // [32][64]
        float* w2_s  = sm + 4096;    // [64]

        int hb  = (bid & 3) * 64;
        int m0  = ((bid >> 2) & 15) * 64;
        int n0  = (bid >> 6) * 64;
        int tn  = tid & 15;          // n base = tn*4
        int tm  = tid >> 4;          // m base = tm*8

        u64 acc[4][4];               // [ni][mpair]
        #pragma unroll
        for (int i = 0; i < 4; i++)
            #pragma unroll
            for (int p = 0; p < 4; p++)
                acc[i][p] = 0ull;

        if (tid < 64) w2_s[tid] = W2[hb + tid];

        int cg = tid & 15;
        int r0 = tid >> 4;

        for (int sc = 0; sc < 2; sc++) {
            int hbase = hb + sc * 32;
            #pragma unroll
            for (int k = 0; k < 4; k++) {
                int hh = k * 8 + r0;
                *(float4*)&hx_s[hh * 64 + cg * 4]  = *(const float4*)&g_hxT[(hbase + hh) * N_ + n0 + cg * 4];
                *(float4*)&heb_s[hh * 64 + cg * 4] = *(const float4*)&g_hebT[(hbase + hh) * M_ + m0 + cg * 4];
            }
            __syncthreads();

            #pragma unroll 4
            for (int hh = 0; hh < 32; hh++) {
                float4 hx4 = *(const float4*)&hx_s[hh * 64 + tn * 4];
                ulonglong2 e0 = *(const ulonglong2*)&heb_s[hh * 64 + tm * 8];
                ulonglong2 e1 = *(const ulonglong2*)&heb_s[hh * 64 + tm * 8 + 4];
                u64 w2p = bcast2(w2_s[sc * 32 + hh]);
                u64 q0 = bcast2(hx4.x);
                u64 q1 = bcast2(hx4.y);
                u64 q2 = bcast2(hx4.z);
                u64 q3 = bcast2(hx4.w);

                relu_fma2(acc[0][0], e0.x, q0, w2p);
                relu_fma2(acc[0][1], e0.y, q0, w2p);
                relu_fma2(acc[0][2], e1.x, q0, w2p);
                relu_fma2(acc[0][3], e1.y, q0, w2p);

                relu_fma2(acc[1][0], e0.x, q1, w2p);
                relu_fma2(acc[1][1], e0.y, q1, w2p);
                relu_fma2(acc[1][2], e1.x, q1, w2p);
                relu_fma2(acc[1][3], e1.y, q1, w2p);

                relu_fma2(acc[2][0], e0.x, q2, w2p);
                relu_fma2(acc[2][1], e0.y, q2, w2p);
                relu_fma2(acc[2][2], e1.x, q2, w2p);
                relu_fma2(acc[2][3], e1.y, q2, w2p);

                relu_fma2(acc[3][0], e0.x, q3, w2p);
                relu_fma2(acc[3][1], e0.y, q3, w2p);
                relu_fma2(acc[3][2], e1.x, q3, w2p);
                relu_fma2(acc[3][3], e1.y, q3, w2p);
            }
            __syncthreads();
        }

        #pragma unroll
        for (int i = 0; i < 4; i++) {
            int n = n0 + tn * 4 + i;
            float2 a = unpack2(acc[i][0]);
            float2 b = unpack2(acc[i][1]);
            float2 c = unpack2(acc[i][2]);
            float2 d = unpack2(acc[i][3]);
            float* dst = &out[n * M_ + m0 + tm * 8];
            asm volatile("red.global.add.v4.f32 [%0], {%1, %2, %3, %4};"
                         :: "l"(dst), "f"(a.x), "f"(a.y), "f"(b.x), "f"(b.y) : "memory");
            asm volatile("red.global.add.v4.f32 [%0], {%1, %2, %3, %4};"
                         :: "l"(dst + 4), "f"(c.x), "f"(c.y), "f"(d.x), "f"(d.y) : "memory");
        }
    }

    gbar(&g_bar[2]);   // ======== barrier C ========

    // ======== phase 4: sigmoid in place + re-zero scratch for next call ===
    {
        int gi = bid * 128 + tid;
        if (gi < (M_ * D_) / 4) ((float4*)g_sum)[gi] = make_float4(0.f, 0.f, 0.f, 0.f);
        if (gi < M_) g_cnt[gi] = 0;
        if (bid == 0 && tid == 0) { g_bar[0] = 0; g_bar[1] = 0; }

        float4* o4 = (float4*)out;
        int i0 = bid * 256 + tid;
        int i1 = bid * 256 + 128 + tid;
        float4 v0, v1;
        asm volatile("ld.global.cg.v4.f32 {%0,%1,%2,%3}, [%4];"
                     : "=f"(v0.x), "=f"(v0.y), "=f"(v0.z), "=f"(v0.w) : "l"((float*)&o4[i0]));
        asm volatile("ld.global.cg.v4.f32 {%0,%1,%2,%3}, [%4];"
                     : "=f"(v1.x), "=f"(v1.y), "=f"(v1.z), "=f"(v1.w) : "l"((float*)&o4[i1]));
        v0.x = sigmoidf_fast(v0.x);
        v0.y = sigmoidf_fast(v0.y);
        v0.z = sigmoidf_fast(v0.z);
        v0.w = sigmoidf_fast(v0.w);
        v1.x = sigmoidf_fast(v1.x);
        v1.y = sigmoidf_fast(v1.y);
        v1.z = sigmoidf_fast(v1.z);
        v1.w = sigmoidf_fast(v1.w);
        o4[i0] = v0;
        o4[i1] = v1;
    }
}

// ---------------- launch ----------------
extern "C" void kernel_launch(void* const* d_in, const int* in_sizes, int n_in,
                              void* d_out, int out_size) {
    const float* X  = (const float*)d_in[0];
    const int*   V  = (const int*)d_in[1];
    const int*   E  = (const int*)d_in[2];
    const float* W1 = (const float*)d_in[3];
    const float* b1 = (const float*)d_in[4];
    const float* W2 = (const float*)d_in[5];
    const float* b2 = (const float*)d_in[6];
    float* out = (float*)d_out;

    k_fused<<<GRID_, 128>>>(X, V, E, W1, b1, W2, b2, out);
}

// round 13
// speedup vs baseline: 1.0401x; 1.0401x over previous
#include <cuda_runtime.h>

#define N_    1024
#define M_    1024
#define D_    128
#define NNZ_  32768
#define H_    256

typedef unsigned long long u64;

// ---------------- device scratch (no allocations allowed) ----------------
// Zero-initialized at module load; k_sig restores the zero state for
// g_sum / g_cnt after each invocation, so every call sees zeroed scratch.
__device__ int   g_cnt[M_];
__device__ __align__(16) float g_sum[M_ * D_];     // raw scatter sums [m][d]
__device__ __align__(16) float g_hxT[H_ * N_];     // [h][n]
__device__ __align__(16) float g_hebT[H_ * M_];    // [h][m]  (includes /cnt and +b1)

// ---------------- small helpers ----------------
__device__ __forceinline__ u64 bcast2(float v) {
    u64 r;
    asm("mov.b64 %0, {%1, %1};" : "=l"(r) : "f"(v));
    return r;
}

__device__ __forceinline__ float2 unpack2(u64 v) {
    float lo, hi;
    asm("mov.b64 {%0, %1}, %2;" : "=f"(lo), "=f"(hi) : "l"(v));
    return make_float2(lo, hi);
}

// acc2 += relu(a2 + b2) * w2   (packed add/fma; relu on the scalar halves)
__device__ __forceinline__ void relu_fma2(u64 &acc, u64 a, u64 b, u64 w) {
    asm("{\n\t"
        ".reg .b64 t;\n\t"
        ".reg .f32 lo, hi;\n\t"
        "add.rn.f32x2 t, %1, %2;\n\t"
        "mov.b64 {lo, hi}, t;\n\t"
        "max.f32 lo, lo, 0f00000000;\n\t"
        "max.f32 hi, hi, 0f00000000;\n\t"
        "mov.b64 t, {lo, hi};\n\t"
        "fma.rn.f32x2 %0, t, %3, %0;\n\t"
        "}"
        : "+l"(acc) : "l"(a), "l"(b), "l"(w));
}

__device__ __forceinline__ float sigmoidf_fast(float x) {
    return 1.0f / (1.0f + __expf(-x));
}

// ---------------- stage 1: scatter (+ init d_out to b2 in extra blocks) --
// blocks [0,1024): out[..] = b2 (REDs then accumulate logits onto b2).
// blocks [1024,5120): one warp per edge, vector-RED into g_sum.
__global__ __launch_bounds__(256) void k_scatter(const float* __restrict__ X,
                                                 const int* __restrict__ V,
                                                 const int* __restrict__ E,
                                                 const float* __restrict__ b2p,
                                                 float* __restrict__ out) {
    int bx = blockIdx.x;
    if (bx < 1024) {
        float b = b2p[0];
        int i = bx * 256 + threadIdx.x;
        ((float4*)out)[i] = make_float4(b, b, b, b);
        return;
    }
    int edge = (bx - 1024) * 8 + (threadIdx.x >> 5);
    int lane = threadIdx.x & 31;
    int e = E[edge];
    int v = V[edge];
    float4 x = *(const float4*)&X[v * D_ + lane * 4];
    float* dst = &g_sum[e * D_ + lane * 4];
    asm volatile("red.global.add.v4.f32 [%0], {%1, %2, %3, %4};"
                 :: "l"(dst), "f"(x.x), "f"(x.y), "f"(x.z), "f"(x.w) : "memory");
    if (lane == 0) atomicAdd(&g_cnt[e], 1);
}

// ---------------- stage 2: the two small GEMMs (fused, transposed output) --
__global__ __launch_bounds__(256) void k_gemm(const float* __restrict__ X,
                                              const float* __restrict__ W1,
                                              const float* __restrict__ b1) {
    int z = blockIdx.z;
    const float* A    = z ? g_sum  : X;
    float*       outT = z ? g_hebT : g_hxT;
    int dof = z ? D_ : 0;

    int n0 = blockIdx.x * 64;
    int h0 = blockIdx.y * 64;

    __shared__ float As[16][65];   // [dk][n]
    __shared__ float Ws[16][64];   // [dk][h]

    int tid = threadIdx.x;
    int tn  = tid & 15;
    int th  = tid >> 4;

    float acc[4][4];
    #pragma unroll
    for (int i = 0; i < 4; i++)
        #pragma unroll
        for (int j = 0; j < 4; j++)
            acc[i][j] = 0.f;

    for (int d0 = 0; d0 < D_; d0 += 16) {
        #pragma unroll
        for (int r = 0; r < 4; r++) {
            int i  = r * 256 + tid;
            int dk = i & 15;
            int nl = i >> 4;
            As[dk][nl] = A[(n0 + nl) * D_ + d0 + dk];
        }
        #pragma unroll
        for (int r = 0; r < 4; r++) {
            int i  = r * 256 + tid;
            int hh = i & 63;
            int dk = i >> 6;
            Ws[dk][hh] = W1[(dof + d0 + dk) * H_ + h0 + hh];
        }
        __syncthreads();
        #pragma unroll
        for (int dk = 0; dk < 16; dk++) {
            float a[4], w[4];
            #pragma unroll
            for (int i = 0; i < 4; i++) a[i] = As[dk][tn * 4 + i];
            #pragma unroll
            for (int j = 0; j < 4; j++) w[j] = Ws[dk][th * 4 + j];
            #pragma unroll
            for (int i = 0; i < 4; i++)
                #pragma unroll
                for (int j = 0; j < 4; j++)
                    acc[i][j] = fmaf(a[i], w[j], acc[i][j]);
        }
        __syncthreads();
    }

    float scale[4] = {1.f, 1.f, 1.f, 1.f};
    if (z) {
        #pragma unroll
        for (int i = 0; i < 4; i++) {
            int c = g_cnt[n0 + tn * 4 + i];
            scale[i] = 1.0f / ((c > 0) ? (float)c : 1.0f);
        }
    }
    #pragma unroll
    for (int j = 0; j < 4; j++) {
        int h = h0 + th * 4 + j;
        float bb = z ? b1[h] : 0.f;
        float4 v = make_float4(acc[0][j] * scale[0] + bb,
                               acc[1][j] * scale[1] + bb,
                               acc[2][j] * scale[2] + bb,
                               acc[3][j] * scale[3] + bb);
        *(float4*)&outT[h * N_ + n0 + tn * 4] = v;
    }
}

// ---------------- stage 3: main N x M x H contraction (h-split) ----------
// grid (H/64, M/64, N/64) = 1024 blocks, 128 threads, all co-resident.
// Scalar-max relu (proven codegen); w2 pre-duplicated in smem.
__global__ __launch_bounds__(128, 7) void k_main(const float* __restrict__ W2,
                                                 float* __restrict__ out) {
    __shared__ __align__(16) float hx_s[32][64];
    __shared__ __align__(16) float heb_s[32][64];
    __shared__ __align__(16) u64   w2d[64];        // duplicated {w,w}

    int hb = blockIdx.x * 64;
    int m0 = blockIdx.y * 64;
    int n0 = blockIdx.z * 64;
    int tid = threadIdx.x;
    int tn  = tid & 15;   // n base = tn*4
    int tm  = tid >> 4;   // m base = tm*8

    u64 acc[4][4];        // [ni][mpair]
    #pragma unroll
    for (int i = 0; i < 4; i++)
        #pragma unroll
        for (int p = 0; p < 4; p++)
            acc[i][p] = 0ull;

    if (tid < 64) w2d[tid] = bcast2(W2[hb + tid]);

    int cg = tid & 15;    // float4 column group for loads
    int r0 = tid >> 4;    // row base for loads (0..7)

    for (int sc = 0; sc < 2; sc++) {
        int hbase = hb + sc * 32;
        #pragma unroll
        for (int k = 0; k < 4; k++) {
            int hh = k * 8 + r0;
            *(float4*)&hx_s[hh][cg * 4]  = *(const float4*)&g_hxT[(hbase + hh) * N_ + n0 + cg * 4];
            *(float4*)&heb_s[hh][cg * 4] = *(const float4*)&g_hebT[(hbase + hh) * M_ + m0 + cg * 4];
        }
        __syncthreads();

        #pragma unroll 4
        for (int hh = 0; hh < 32; hh++) {
            float4 hx4 = *(const float4*)&hx_s[hh][tn * 4];
            ulonglong2 e0 = *(const ulonglong2*)&heb_s[hh][tm * 8];
            ulonglong2 e1 = *(const ulonglong2*)&heb_s[hh][tm * 8 + 4];
            u64 w2p = w2d[sc * 32 + hh];
            u64 q0 = bcast2(hx4.x);
            u64 q1 = bcast2(hx4.y);
            u64 q2 = bcast2(hx4.z);
            u64 q3 = bcast2(hx4.w);

            relu_fma2(acc[0][0], e0.x, q0, w2p);
            relu_fma2(acc[0][1], e0.y, q0, w2p);
            relu_fma2(acc[0][2], e1.x, q0, w2p);
            relu_fma2(acc[0][3], e1.y, q0, w2p);

            relu_fma2(acc[1][0], e0.x, q1, w2p);
            relu_fma2(acc[1][1], e0.y, q1, w2p);
            relu_fma2(acc[1][2], e1.x, q1, w2p);
            relu_fma2(acc[1][3], e1.y, q1, w2p);

            relu_fma2(acc[2][0], e0.x, q2, w2p);
            relu_fma2(acc[2][1], e0.y, q2, w2p);
            relu_fma2(acc[2][2], e1.x, q2, w2p);
            relu_fma2(acc[2][3], e1.y, q2, w2p);

            relu_fma2(acc[3][0], e0.x, q3, w2p);
            relu_fma2(acc[3][1], e0.y, q3, w2p);
            relu_fma2(acc[3][2], e1.x, q3, w2p);
            relu_fma2(acc[3][3], e1.y, q3, w2p);
        }
        __syncthreads();
    }

    // epilogue: vector-RED partial logits into out[n][m] (on top of b2 init)
    #pragma unroll
    for (int i = 0; i < 4; i++) {
        int n = n0 + tn * 4 + i;
        float2 a = unpack2(acc[i][0]);
        float2 b = unpack2(acc[i][1]);
        float2 c = unpack2(acc[i][2]);
        float2 d = unpack2(acc[i][3]);
        float* dst = &out[n * M_ + m0 + tm * 8];
        asm volatile("red.global.add.v4.f32 [%0], {%1, %2, %3, %4};"
                     :: "l"(dst), "f"(a.x), "f"(a.y), "f"(b.x), "f"(b.y) : "memory");
        asm volatile("red.global.add.v4.f32 [%0], {%1, %2, %3, %4};"
                     :: "l"(dst + 4), "f"(c.x), "f"(c.y), "f"(d.x), "f"(d.y) : "memory");
    }
}

// ---------------- stage 4: sigmoid epilogue (512 blocks) + re-zero -------
// 512 blocks x 256 threads, 2 coalesced float4s per thread, loads batched.
__global__ __launch_bounds__(256) void k_sig(float* __restrict__ out) {
    int tid  = threadIdx.x;
    int base = blockIdx.x * 512 + tid;      // float4 index
    float4* o4 = (float4*)out;

    float4 v0 = o4[base];
    float4 v1 = o4[base + 256];

    // restore scratch zero-state for the next invocation (overlaps MUFU)
    int i = blockIdx.x * 256 + tid;
    if (i < (M_ * D_) / 4) ((float4*)g_sum)[i] = make_float4(0.f, 0.f, 0.f, 0.f);
    if (i < M_) g_cnt[i] = 0;

    v0.x = sigmoidf_fast(v0.x);
    v0.y = sigmoidf_fast(v0.y);
    v0.z = sigmoidf_fast(v0.z);
    v0.w = sigmoidf_fast(v0.w);
    v1.x = sigmoidf_fast(v1.x);
    v1.y = sigmoidf_fast(v1.y);
    v1.z = sigmoidf_fast(v1.z);
    v1.w = sigmoidf_fast(v1.w);

    o4[base]       = v0;
    o4[base + 256] = v1;
}

// ---------------- launch ----------------
extern "C" void kernel_launch(void* const* d_in, const int* in_sizes, int n_in,
                              void* d_out, int out_size) {
    const float* X  = (const float*)d_in[0];
    const int*   V  = (const int*)d_in[1];
    const int*   E  = (const int*)d_in[2];
    const float* W1 = (const float*)d_in[3];
    const float* b1 = (const float*)d_in[4];
    const float* W2 = (const float*)d_in[5];
    const float* b2 = (const float*)d_in[6];
    float* out = (float*)d_out;

    k_scatter<<<1024 + NNZ_ / 8, 256>>>(X, V, E, b2, out);
    k_gemm<<<dim3(N_ / 64, H_ / 64, 2), 256>>>(X, W1, b1);
    k_main<<<dim3(H_ / 64, M_ / 64, N_ / 64), 128>>>(W2, out);
    k_sig<<<512, 256>>>(out);
}

// round 14
// speedup vs baseline: 1.0828x; 1.0411x over previous
#include <cuda_runtime.h>

#define N_    1024
#define M_    1024
#define D_    128
#define NNZ_  32768
#define H_    256

typedef unsigned long long u64;

// ---------------- device scratch (no allocations allowed) ----------------
// Zero-initialized at module load; k_sig restores the zero state for
// g_sum / g_cnt after each invocation, so every call sees zeroed scratch.
__device__ int   g_cnt[M_];
__device__ __align__(16) float g_sum[M_ * D_];     // raw scatter sums [m][d]
__device__ __align__(16) float g_hxT[H_ * N_];     // [h][n]
__device__ __align__(16) float g_hebT[H_ * M_];    // [h][m]  (includes /cnt and +b1)

// ---------------- small helpers ----------------
__device__ __forceinline__ u64 bcast2(float v) {
    u64 r;
    asm("mov.b64 %0, {%1, %1};" : "=l"(r) : "f"(v));
    return r;
}

__device__ __forceinline__ float2 unpack2(u64 v) {
    float lo, hi;
    asm("mov.b64 {%0, %1}, %2;" : "=f"(lo), "=f"(hi) : "l"(v));
    return make_float2(lo, hi);
}

// acc2 += relu(a2 + b2) * w2   (packed add/fma; relu on the scalar halves)
__device__ __forceinline__ void relu_fma2(u64 &acc, u64 a, u64 b, u64 w) {
    asm("{\n\t"
        ".reg .b64 t;\n\t"
        ".reg .f32 lo, hi;\n\t"
        "add.rn.f32x2 t, %1, %2;\n\t"
        "mov.b64 {lo, hi}, t;\n\t"
        "max.f32 lo, lo, 0f00000000;\n\t"
        "max.f32 hi, hi, 0f00000000;\n\t"
        "mov.b64 t, {lo, hi};\n\t"
        "fma.rn.f32x2 %0, t, %3, %0;\n\t"
        "}"
        : "+l"(acc) : "l"(a), "l"(b), "l"(w));
}

// sigmoid(x) = 0.5*tanh(0.5x) + 0.5 — ONE MUFU op instead of EX2+RCP
__device__ __forceinline__ float sigmoid_tanh(float x) {
    float t;
    asm("tanh.approx.f32 %0, %1;" : "=f"(t) : "f"(x * 0.5f));
    return fmaf(t, 0.5f, 0.5f);
}

// ---------------- stage 1: scatter (+ init d_out to b2 in extra blocks) --
// blocks [0,1024): out[..] = b2 (REDs then accumulate logits onto b2).
// blocks [1024,5120): one warp per edge, vector-RED into g_sum.
__global__ __launch_bounds__(256) void k_scatter(const float* __restrict__ X,
                                                 const int* __restrict__ V,
                                                 const int* __restrict__ E,
                                                 const float* __restrict__ b2p,
                                                 float* __restrict__ out) {
    int bx = blockIdx.x;
    if (bx < 1024) {
        float b = b2p[0];
        int i = bx * 256 + threadIdx.x;
        ((float4*)out)[i] = make_float4(b, b, b, b);
        return;
    }
    int edge = (bx - 1024) * 8 + (threadIdx.x >> 5);
    int lane = threadIdx.x & 31;
    int e = E[edge];
    int v = V[edge];
    float4 x = *(const float4*)&X[v * D_ + lane * 4];
    float* dst = &g_sum[e * D_ + lane * 4];
    asm volatile("red.global.add.v4.f32 [%0], {%1, %2, %3, %4};"
                 :: "l"(dst), "f"(x.x), "f"(x.y), "f"(x.z), "f"(x.w) : "memory");
    if (lane == 0) atomicAdd(&g_cnt[e], 1);
}

// ---------------- stage 2: the two small GEMMs (fused, transposed output) --
__global__ __launch_bounds__(256) void k_gemm(const float* __restrict__ X,
                                              const float* __restrict__ W1,
                                              const float* __restrict__ b1) {
    int z = blockIdx.z;
    const float* A    = z ? g_sum  : X;
    float*       outT = z ? g_hebT : g_hxT;
    int dof = z ? D_ : 0;

    int n0 = blockIdx.x * 64;
    int h0 = blockIdx.y * 64;

    __shared__ float As[16][65];   // [dk][n]
    __shared__ float Ws[16][64];   // [dk][h]

    int tid = threadIdx.x;
    int tn  = tid & 15;
    int th  = tid >> 4;

    float acc[4][4];
    #pragma unroll
    for (int i = 0; i < 4; i++)
        #pragma unroll
        for (int j = 0; j < 4; j++)
            acc[i][j] = 0.f;

    for (int d0 = 0; d0 < D_; d0 += 16) {
        #pragma unroll
        for (int r = 0; r < 4; r++) {
            int i  = r * 256 + tid;
            int dk = i & 15;
            int nl = i >> 4;
            As[dk][nl] = A[(n0 + nl) * D_ + d0 + dk];
        }
        #pragma unroll
        for (int r = 0; r < 4; r++) {
            int i  = r * 256 + tid;
            int hh = i & 63;
            int dk = i >> 6;
            Ws[dk][hh] = W1[(dof + d0 + dk) * H_ + h0 + hh];
        }
        __syncthreads();
        #pragma unroll
        for (int dk = 0; dk < 16; dk++) {
            float a[4], w[4];
            #pragma unroll
            for (int i = 0; i < 4; i++) a[i] = As[dk][tn * 4 + i];
            #pragma unroll
            for (int j = 0; j < 4; j++) w[j] = Ws[dk][th * 4 + j];
            #pragma unroll
            for (int i = 0; i < 4; i++)
                #pragma unroll
                for (int j = 0; j < 4; j++)
                    acc[i][j] = fmaf(a[i], w[j], acc[i][j]);
        }
        __syncthreads();
    }

    float scale[4] = {1.f, 1.f, 1.f, 1.f};
    if (z) {
        #pragma unroll
        for (int i = 0; i < 4; i++) {
            int c = g_cnt[n0 + tn * 4 + i];
            scale[i] = 1.0f / ((c > 0) ? (float)c : 1.0f);
        }
    }
    #pragma unroll
    for (int j = 0; j < 4; j++) {
        int h = h0 + th * 4 + j;
        float bb = z ? b1[h] : 0.f;
        float4 v = make_float4(acc[0][j] * scale[0] + bb,
                               acc[1][j] * scale[1] + bb,
                               acc[2][j] * scale[2] + bb,
                               acc[3][j] * scale[3] + bb);
        *(float4*)&outT[h * N_ + n0 + tn * 4] = v;
    }
}

// ---------------- stage 3: main N x M x H contraction (h-split) ----------
// grid (H/64, M/64, N/64) = 1024 blocks, 128 threads, all co-resident.
// Byte-exact R7 version (proven 29.0us / 49.6 total).
__global__ __launch_bounds__(128, 7) void k_main(const float* __restrict__ W2,
                                                 float* __restrict__ out) {
    __shared__ __align__(16) float hx_s[32][64];
    __shared__ __align__(16) float heb_s[32][64];
    __shared__ float w2_s[64];

    int hb = blockIdx.x * 64;
    int m0 = blockIdx.y * 64;
    int n0 = blockIdx.z * 64;
    int tid = threadIdx.x;
    int tn  = tid & 15;   // n base = tn*4
    int tm  = tid >> 4;   // m base = tm*8

    u64 acc[4][4];        // [ni][mpair]
    #pragma unroll
    for (int i = 0; i < 4; i++)
        #pragma unroll
        for (int p = 0; p < 4; p++)
            acc[i][p] = 0ull;

    if (tid < 64) w2_s[tid] = W2[hb + tid];

    int cg = tid & 15;    // float4 column group for loads
    int r0 = tid >> 4;    // row base for loads (0..7)

    for (int sc = 0; sc < 2; sc++) {
        int hbase = hb + sc * 32;
        #pragma unroll
        for (int k = 0; k < 4; k++) {
            int hh = k * 8 + r0;
            *(float4*)&hx_s[hh][cg * 4]  = *(const float4*)&g_hxT[(hbase + hh) * N_ + n0 + cg * 4];
            *(float4*)&heb_s[hh][cg * 4] = *(const float4*)&g_hebT[(hbase + hh) * M_ + m0 + cg * 4];
        }
        __syncthreads();

        #pragma unroll 4
        for (int hh = 0; hh < 32; hh++) {
            float4 hx4 = *(const float4*)&hx_s[hh][tn * 4];
            ulonglong2 e0 = *(const ulonglong2*)&heb_s[hh][tm * 8];
            ulonglong2 e1 = *(const ulonglong2*)&heb_s[hh][tm * 8 + 4];
            u64 w2p = bcast2(w2_s[sc * 32 + hh]);
            u64 q0 = bcast2(hx4.x);
            u64 q1 = bcast2(hx4.y);
            u64 q2 = bcast2(hx4.z);
            u64 q3 = bcast2(hx4.w);

            relu_fma2(acc[0][0], e0.x, q0, w2p);
            relu_fma2(acc[0][1], e0.y, q0, w2p);
            relu_fma2(acc[0][2], e1.x, q0, w2p);
            relu_fma2(acc[0][3], e1.y, q0, w2p);

            relu_fma2(acc[1][0], e0.x, q1, w2p);
            relu_fma2(acc[1][1], e0.y, q1, w2p);
            relu_fma2(acc[1][2], e1.x, q1, w2p);
            relu_fma2(acc[1][3], e1.y, q1, w2p);

            relu_fma2(acc[2][0], e0.x, q2, w2p);
            relu_fma2(acc[2][1], e0.y, q2, w2p);
            relu_fma2(acc[2][2], e1.x, q2, w2p);
            relu_fma2(acc[2][3], e1.y, q2, w2p);

            relu_fma2(acc[3][0], e0.x, q3, w2p);
            relu_fma2(acc[3][1], e0.y, q3, w2p);
            relu_fma2(acc[3][2], e1.x, q3, w2p);
            relu_fma2(acc[3][3], e1.y, q3, w2p);
        }
        __syncthreads();
    }

    // epilogue: vector-RED partial logits into out[n][m] (on top of b2 init)
    #pragma unroll
    for (int i = 0; i < 4; i++) {
        int n = n0 + tn * 4 + i;
        float2 a = unpack2(acc[i][0]);
        float2 b = unpack2(acc[i][1]);
        float2 c = unpack2(acc[i][2]);
        float2 d = unpack2(acc[i][3]);
        float* dst = &out[n * M_ + m0 + tm * 8];
        asm volatile("red.global.add.v4.f32 [%0], {%1, %2, %3, %4};"
                     :: "l"(dst), "f"(a.x), "f"(a.y), "f"(b.x), "f"(b.y) : "memory");
        asm volatile("red.global.add.v4.f32 [%0], {%1, %2, %3, %4};"
                     :: "l"(dst + 4), "f"(c.x), "f"(c.y), "f"(d.x), "f"(d.y) : "memory");
    }
}

// ---------------- stage 4: sigmoid epilogue (tanh.approx) + re-zero ------
// 512 blocks x 256 threads, 2 coalesced float4s per thread.
// sigmoid via single-MUFU tanh.approx: halves the XU-pipe work.
__global__ __launch_bounds__(256) void k_sig(float* __restrict__ out) {
    int tid  = threadIdx.x;
    int base = blockIdx.x * 512 + tid;      // float4 index
    float4* o4 = (float4*)out;

    float4 v0 = o4[base];
    float4 v1 = o4[base + 256];

    // restore scratch zero-state for the next invocation (overlaps XU work)
    int i = blockIdx.x * 256 + tid;
    if (i < (M_ * D_) / 4) ((float4*)g_sum)[i] = make_float4(0.f, 0.f, 0.f, 0.f);
    if (i < M_) g_cnt[i] = 0;

    v0.x = sigmoid_tanh(v0.x);
    v0.y = sigmoid_tanh(v0.y);
    v0.z = sigmoid_tanh(v0.z);
    v0.w = sigmoid_tanh(v0.w);
    v1.x = sigmoid_tanh(v1.x);
    v1.y = sigmoid_tanh(v1.y);
    v1.z = sigmoid_tanh(v1.z);
    v1.w = sigmoid_tanh(v1.w);

    o4[base]       = v0;
    o4[base + 256] = v1;
}

// ---------------- launch ----------------
extern "C" void kernel_launch(void* const* d_in, const int* in_sizes, int n_in,
                              void* d_out, int out_size) {
    const float* X  = (const float*)d_in[0];
    const int*   V  = (const int*)d_in[1];
    const int*   E  = (const int*)d_in[2];
    const float* W1 = (const float*)d_in[3];
    const float* b1 = (const float*)d_in[4];
    const float* W2 = (const float*)d_in[5];
    const float* b2 = (const float*)d_in[6];
    float* out = (float*)d_out;

    k_scatter<<<1024 + NNZ_ / 8, 256>>>(X, V, E, b2, out);
    k_gemm<<<dim3(N_ / 64, H_ / 64, 2), 256>>>(X, W1, b1);
    k_main<<<dim3(H_ / 64, M_ / 64, N_ / 64), 128>>>(W2, out);
    k_sig<<<512, 256>>>(out);
}